// round 16
// baseline (speedup 1.0000x reference)
#include <cuda_runtime.h>
#include <cuda_bf16.h>
#include <cuda_fp16.h>
#include <cstdint>
#include <cstddef>

// ---------------- problem dims ----------------
constexpr int TT    = 4;
constexpr int BROWS = 8192;
constexpr int DD    = 512;
constexpr int HH    = 2048;
constexpr int KQ1   = 1024;           // layer1 int8 K: [q(lx) | q(x)]
constexpr int KH1   = 512;            // layer1 fp16 K (hi*hi)
constexpr int KA2   = 2048;           // layer2 A cols (s1 int8, wraps)
constexpr int KB2   = 4096;           // layer2 K: 2 digit planes x 2048 int8

// layer1 scales (fold constraint: 1/(IXL*IWH) == 1/(IXH*IWL), exact)
constexpr float IXH = 127.0f / 8.0f;
constexpr float IXL = 40000.0f;
constexpr float IWH = 127.0f / 0.32f;
constexpr float IWL = 1000000.0f;
constexpr float CFOLD = 8.0f / (127.0f * 1000000.0f);
constexpr float EPS1 = 2.5e-4f;
constexpr float W2SCALE = 1.0f / 32768.0f;
constexpr float EPS2 = 4e-3f;

// ---- layer1 tile: CTA 32 x 128 x 4t, 8 warps of 16x32, STG=3, 2 CTAs/SM ----
constexpr int MS1 = 32, TN1 = 128, STG = 3;
constexpr uint32_t A1_STAGE = 16384;
constexpr uint32_t B1_STAGE = 16384;
constexpr uint32_t SM1_B = STG * A1_STAGE;
constexpr uint32_t SMEM1 = STG * (A1_STAGE + B1_STAGE);   // 98304

// ---- layer2 tile ----
constexpr int MS2 = 32, TN2 = 128, BK2 = 128;
constexpr uint32_t A2_STAGE = 16384;
constexpr uint32_t B2_STAGE = 16384;
constexpr uint32_t SM2_B = STG * A2_STAGE;
constexpr uint32_t SMEM2 = STG * (A2_STAGE + B2_STAGE);   // 98304

// ---------------- scratch ----------------
__device__ __half  g_xh[(size_t)TT * BROWS * KH1];
__device__ int8_t  g_xq[(size_t)TT * BROWS * KQ1];
__device__ __half  g_w1h[(size_t)HH * KH1];
__device__ int8_t  g_w1q[(size_t)HH * KQ1];
__device__ int8_t  g_w2[(size_t)DD * KB2];
__device__ int8_t  g_s1[(size_t)TT * BROWS * HH];
constexpr int LCAP = 1 << 22;
__device__ int g_cnt1, g_cnt2;
__device__ int g_list1[LCAP];
__device__ int g_list2[LCAP];

// ---------------- PTX helpers ----------------
__device__ __forceinline__ uint32_t smem_u32(const void* p) {
    uint32_t a;
    asm("{ .reg .u64 t; cvta.to.shared.u64 t, %1; cvt.u32.u64 %0, t; }" : "=r"(a) : "l"(p));
    return a;
}
#define CP_ASYNC16(dst, src) \
    asm volatile("cp.async.cg.shared.global [%0], [%1], 16;" :: "r"(dst), "l"(src) : "memory")
#define CP_COMMIT() asm volatile("cp.async.commit_group;" ::: "memory")

#define LDSM_X4(r0, r1, r2, r3, addr)                                        \
    asm volatile("ldmatrix.sync.aligned.m8n8.x4.shared.b16 {%0,%1,%2,%3}, [%4];" \
        : "=r"(r0), "=r"(r1), "=r"(r2), "=r"(r3) : "r"(addr))

#define MMAF16(d, a, b)                                                      \
    asm volatile("mma.sync.aligned.m16n8k16.row.col.f32.f16.f16.f32 "        \
        "{%0,%1,%2,%3}, {%4,%5,%6,%7}, {%8,%9}, {%0,%1,%2,%3};"              \
        : "+f"((d)[0]), "+f"((d)[1]), "+f"((d)[2]), "+f"((d)[3])             \
        : "r"((a)[0]), "r"((a)[1]), "r"((a)[2]), "r"((a)[3]),                \
          "r"((b)[0]), "r"((b)[1]))

#define IMMA16832(d, a, b)                                                   \
    asm volatile("mma.sync.aligned.m16n8k32.row.col.s32.s8.s8.s32 "          \
        "{%0,%1,%2,%3}, {%4,%5,%6,%7}, {%8,%9}, {%0,%1,%2,%3};"              \
        : "+r"((d)[0]), "+r"((d)[1]), "+r"((d)[2]), "+r"((d)[3])             \
        : "r"((a)[0]), "r"((a)[1]), "r"((a)[2]), "r"((a)[3]),                \
          "r"((b)[0]), "r"((b)[1]))

__device__ __forceinline__ uint32_t sw_off(uint32_t row, uint32_t kseg) {
    return row * 128 + ((kseg ^ (row & 7)) << 4);
}
__device__ __forceinline__ int8_t q8(float v, float inv) {
    int q = __float2int_rn(v * inv);
    q = max(-127, min(127, q));
    return (int8_t)q;
}
// warp-aggregated flag push
__device__ __forceinline__ void push_flag(bool flag, int val, int* cnt, int* list) {
    unsigned bal = __ballot_sync(0xFFFFFFFF, flag);
    if (!bal) return;
    int leader = __ffs(bal) - 1;
    int lane = threadIdx.x & 31;
    int base = 0;
    if (lane == leader) base = atomicAdd(cnt, __popc(bal));
    base = __shfl_sync(0xFFFFFFFF, base, leader);
    if (flag) {
        int idx = base + __popc(bal & ((1u << lane) - 1));
        if (idx < LCAP) list[idx] = val;
    }
}

// ---------------- fused prep kernel ----------------
// blocks [0,16384): x split/quant; [16384,20480): w1; [20480,24576): w2
__global__ void prep_all(const float4* __restrict__ x,
                         __half* __restrict__ xh, int8_t* __restrict__ xq,
                         const float* __restrict__ w1,
                         __half* __restrict__ wh, int8_t* __restrict__ wq,
                         const float* __restrict__ w2, int8_t* __restrict__ o2)
{
    if (blockIdx.x < 16384) {
        if (blockIdx.x == 0 && threadIdx.x == 0) { g_cnt1 = 0; g_cnt2 = 0; }
        size_t i = (size_t)blockIdx.x * 256 + threadIdx.x;   // 32768*128 float4
        float4 v = x[i];
        int r = (int)(i >> 7);
        int d = ((int)i & 127) * 4;
        __half h0 = __float2half_rn(v.x), h1 = __float2half_rn(v.y);
        __half h2 = __float2half_rn(v.z), h3 = __float2half_rn(v.w);
        __half2* hp = (__half2*)(xh + (size_t)r * KH1 + d);
        hp[0] = __halves2half2(h0, h1);
        hp[1] = __halves2half2(h2, h3);
        float l0 = v.x - __half2float(h0), l1 = v.y - __half2float(h1);
        float l2 = v.z - __half2float(h2), l3 = v.w - __half2float(h3);
        char4 ql = make_char4(q8(l0, IXL), q8(l1, IXL), q8(l2, IXL), q8(l3, IXL));
        char4 qx = make_char4(q8(v.x, IXH), q8(v.y, IXH), q8(v.z, IXH), q8(v.w, IXH));
        *(char4*)(xq + (size_t)r * KQ1 + d)       = ql;
        *(char4*)(xq + (size_t)r * KQ1 + 512 + d) = qx;
    } else if (blockIdx.x < 20480) {
        size_t i = (size_t)(blockIdx.x - 16384) * 256 + threadIdx.x;   // 2048*512
        int r = (int)(i >> 9);
        int d = (int)(i & 511);
        float v = w1[i];
        __half hb = __float2half_rn(v);
        float hi = __half2float(hb);
        wh[(size_t)r * KH1 + d] = hb;
        wq[(size_t)r * KQ1 + d]       = q8(hi, IWH);
        wq[(size_t)r * KQ1 + 512 + d] = q8(v - hi, IWL);
    } else {
        size_t i = (size_t)(blockIdx.x - 20480) * 256 + threadIdx.x;   // 512*2048
        int r = (int)(i >> 11);
        int c = (int)(i & 2047);
        int v = (int)lrintf(w2[i] * 32768.0f);
        v = max(-8192, min(8192, v));
        int d0 = ((v & 127) ^ 64) - 64;
        int d1 = (v - d0) >> 7;
        size_t base = (size_t)r * KB2;
        o2[base + c]        = (int8_t)d1;
        o2[base + 2048 + c] = (int8_t)d0;
    }
}

// ---------------- layer1: unified int8+fp16 pipeline, 2 CTAs/SM ----------------
__global__ __launch_bounds__(256, 2)
void gemm_plif_l1(const void* __restrict__ Aq, const void* __restrict__ Bq,
                  const void* __restrict__ Ah, const void* __restrict__ Bh,
                  const float* __restrict__ alphap,
                  int8_t* __restrict__ outp)
{
    extern __shared__ __align__(128) unsigned char smem_raw[];
    const uint32_t sbase = smem_u32(smem_raw);

    const int tid  = threadIdx.x;
    const int lane = tid & 31;
    const int wid  = tid >> 5;
    const int wm   = wid & 1;
    const int wn   = wid >> 1;
    const int sm_w = wm * 16;
    const int nn_w = wn * 32;

    const int bm0 = blockIdx.x * MS1;
    const int bn0 = blockIdx.y * TN1;

    const int a_row_l = lane & 15;
    const int a_ks_l  = lane >> 4;
    const int b_row_l = (lane & 7) + ((lane & 16) >> 1);
    const int b_ks_l  = (lane >> 3) & 1;

    // precomputed loader offsets (chunk-invariant)
    uint32_t ag[4], as[4], bg[4], bs[4];
    #pragma unroll
    for (int j = 0; j < 4; j++) {
        int i = tid + j * 256;
        int kseg = i & 7, site = (i >> 3) & 31, t = i >> 8;
        ag[j] = (uint32_t)((t * BROWS + bm0 + site) * 1024 + kseg * 16);
        as[j] = (uint32_t)(t * 4096 + sw_off(site, kseg));
        int n = i >> 3;
        bg[j] = (uint32_t)((bn0 + n) * 1024 + kseg * 16);
        bs[j] = sw_off(n, kseg);
    }

    auto load_chunk = [&](int cc, int buf) {
        const char* Ab = (const char*)((cc < 8) ? Aq : Ah);
        const char* Bb = (const char*)((cc < 8) ? Bq : Bh);
        const uint32_t bcol = (cc & 7) * 128;
        const uint32_t abase = sbase + buf * A1_STAGE;
        const uint32_t bbase = sbase + SM1_B + buf * B1_STAGE;
        #pragma unroll
        for (int j = 0; j < 4; j++)
            CP_ASYNC16(abase + as[j], Ab + ag[j] + bcol);
        #pragma unroll
        for (int j = 0; j < 4; j++)
            CP_ASYNC16(bbase + bs[j], Bb + bg[j] + bcol);
        CP_COMMIT();
    };

    float accf[TT][4][4];
    load_chunk(0, 0);
    load_chunk(1, 1);

    {   // ---- int8 phase: chunks 0-7 ----
        int acci[TT][4][4];
        #pragma unroll
        for (int t = 0; t < TT; t++)
            #pragma unroll
            for (int n = 0; n < 4; n++)
                #pragma unroll
                for (int e = 0; e < 4; e++) acci[t][n][e] = 0;

        int buf = 0, pbuf = 2;
        for (int cc = 0; cc < 8; cc++) {
            asm volatile("cp.async.wait_group 1;" ::: "memory");
            __syncthreads();
            load_chunk(cc + 2, pbuf);

            #pragma unroll
            for (int ks = 0; ks < 4; ks++) {
                uint32_t b[4][2];
                #pragma unroll
                for (int p = 0; p < 2; p++) {
                    uint32_t addr = sbase + SM1_B + buf * B1_STAGE +
                        sw_off(nn_w + p * 16 + b_row_l, 2 * ks + b_ks_l);
                    LDSM_X4(b[2*p][0], b[2*p][1], b[2*p+1][0], b[2*p+1][1], addr);
                }
                uint32_t a[TT][4];
                #pragma unroll
                for (int t = 0; t < TT; t++) {
                    uint32_t addr = sbase + buf * A1_STAGE + t * 4096 +
                        sw_off(sm_w + a_row_l, 2 * ks + a_ks_l);
                    LDSM_X4(a[t][0], a[t][1], a[t][2], a[t][3], addr);
                }
                #pragma unroll
                for (int t = 0; t < TT; t++)
                    #pragma unroll
                    for (int n = 0; n < 4; n++)
                        IMMA16832(acci[t][n], a[t], b[n]);
            }
            buf = (buf == STG - 1) ? 0 : buf + 1;
            pbuf = (pbuf == STG - 1) ? 0 : pbuf + 1;
        }
        #pragma unroll
        for (int t = 0; t < TT; t++)
            #pragma unroll
            for (int n = 0; n < 4; n++)
                #pragma unroll
                for (int e = 0; e < 4; e++)
                    accf[t][n][e] = CFOLD * (float)acci[t][n][e];
    }

    // ---- fp16 phase: chunks 8-15, same ring, no drain ----
    {
        int buf = 8 % STG, pbuf = 10 % STG;
        for (int cc = 8; cc < 16; cc++) {
            if (cc < 15) asm volatile("cp.async.wait_group 1;" ::: "memory");
            else         asm volatile("cp.async.wait_group 0;" ::: "memory");
            __syncthreads();
            if (cc + 2 < 16) load_chunk(cc + 2, pbuf);

            #pragma unroll
            for (int ks = 0; ks < 4; ks++) {
                uint32_t b[4][2];
                #pragma unroll
                for (int p = 0; p < 2; p++) {
                    uint32_t addr = sbase + SM1_B + buf * B1_STAGE +
                        sw_off(nn_w + p * 16 + b_row_l, 2 * ks + b_ks_l);
                    LDSM_X4(b[2*p][0], b[2*p][1], b[2*p+1][0], b[2*p+1][1], addr);
                }
                uint32_t a[TT][4];
                #pragma unroll
                for (int t = 0; t < TT; t++) {
                    uint32_t addr = sbase + buf * A1_STAGE + t * 4096 +
                        sw_off(sm_w + a_row_l, 2 * ks + a_ks_l);
                    LDSM_X4(a[t][0], a[t][1], a[t][2], a[t][3], addr);
                }
                #pragma unroll
                for (int t = 0; t < TT; t++)
                    #pragma unroll
                    for (int n = 0; n < 4; n++)
                        MMAF16(accf[t][n], a[t], b[n]);
            }
            buf = (buf == STG - 1) ? 0 : buf + 1;
            pbuf = (pbuf == STG - 1) ? 0 : pbuf + 1;
        }
    }

    // ---- epilogue: scan, store spikes, flag tight margins ----
    const float alpha = alphap[0];
    const int row_in_m = lane >> 2;
    const int col_pair = (lane & 3) * 2;

    #pragma unroll
    for (int n = 0; n < 4; n++)
        #pragma unroll
        for (int rh = 0; rh < 2; rh++) {
            const int site = bm0 + sm_w + row_in_m + rh * 8;
            const int col  = bn0 + nn_w + n * 8 + col_pair;
            float v0 = 0.f, v1 = 0.f, m0 = 1e9f, m1 = 1e9f;
            #pragma unroll
            for (int t = 0; t < TT; t++) {
                v0 += alpha * (accf[t][n][rh * 2]     - v0);
                v1 += alpha * (accf[t][n][rh * 2 + 1] - v1);
                m0 = fminf(m0, fabsf(v0 - 1.0f));
                m1 = fminf(m1, fabsf(v1 - 1.0f));
                bool s0 = (v0 >= 1.0f), s1 = (v1 >= 1.0f);
                v0 = s0 ? 0.f : v0;
                v1 = s1 ? 0.f : v1;
                char2 pk;
                pk.x = s0 ? 1 : 0;
                pk.y = s1 ? 1 : 0;
                *(char2*)(outp + ((size_t)t * BROWS + site) * HH + col) = pk;
            }
            push_flag(m0 < EPS1, site * 2048 + col,     &g_cnt1, g_list1);
            push_flag(m1 < EPS1, site * 2048 + col + 1, &g_cnt1, g_list1);
        }
}

// ---------------- repair1: t-parallel exact fp32 recompute ----------------
// 4 groups of 8 lanes, one timestep each (4x memory-level parallelism).
__global__ void repair_l1(const float* __restrict__ xraw,
                          const float* __restrict__ w1raw,
                          const float* __restrict__ alphap,
                          int8_t* __restrict__ s1)
{
    const int total = min(g_cnt1, LCAP);
    const float alpha = alphap[0];
    const int lane = threadIdx.x & 31;
    const int tg   = lane >> 3;          // timestep group 0..3
    const int gl   = lane & 7;           // lane within group
    const int nwarp = (gridDim.x * blockDim.x) >> 5;
    for (int w = (blockIdx.x * blockDim.x + threadIdx.x) >> 5; w < total; w += nwarp) {
        const int e = g_list1[w];
        const int site = e >> 11, neuron = e & 2047;
        const float4* wp = (const float4*)(w1raw + (size_t)neuron * 512);
        const float4* xp = (const float4*)(xraw + ((size_t)tg * BROWS + site) * 512);
        float p = 0.f;
        #pragma unroll
        for (int k = 0; k < 16; k++) {
            float4 xv = xp[gl + k * 8], wv = wp[gl + k * 8];
            p += xv.x * wv.x + xv.y * wv.y + xv.z * wv.z + xv.w * wv.w;
        }
        // reduce within 8-lane group
        p += __shfl_xor_sync(0xFFFFFFFF, p, 4);
        p += __shfl_xor_sync(0xFFFFFFFF, p, 2);
        p += __shfl_xor_sync(0xFFFFFFFF, p, 1);
        // lane 0 gathers h[t] from lanes 0,8,16,24 and scans
        float h0 = __shfl_sync(0xFFFFFFFF, p, 0);
        float h1 = __shfl_sync(0xFFFFFFFF, p, 8);
        float h2 = __shfl_sync(0xFFFFFFFF, p, 16);
        float h3 = __shfl_sync(0xFFFFFFFF, p, 24);
        if (lane == 0) {
            float h[4] = {h0, h1, h2, h3};
            float v = 0.f;
            #pragma unroll
            for (int t = 0; t < TT; t++) {
                v += alpha * (h[t] - v);
                bool s = (v >= 1.0f);
                s1[((size_t)t * BROWS + site) * HH + neuron] = s ? 1 : 0;
                v = s ? 0.f : v;
            }
        }
    }
}

// ---------------- layer2: int8 IMMA 2-digit + PLIF + flag, 2 CTAs/SM ----------------
__global__ __launch_bounds__(256, 2)
void gemm_plif_l2(const int8_t* __restrict__ A,
                  const int8_t* __restrict__ Bw,
                  const float* __restrict__ alphap,
                  float* __restrict__ outp)
{
    extern __shared__ __align__(128) unsigned char smem_raw[];
    const uint32_t sbase = smem_u32(smem_raw);

    const int tid  = threadIdx.x;
    const int lane = tid & 31;
    const int wid  = tid >> 5;
    const int wm   = wid & 1;
    const int wn   = wid >> 1;
    const int sm_w = wm * 16;
    const int nn_w = wn * 32;

    const int bm0 = blockIdx.x * MS2;
    const int bn0 = blockIdx.y * TN2;
    const int NC  = KB2 / BK2;          // 32; digit fold at cc==15

    const int a_row_l = lane & 15;
    const int a_ks_l  = lane >> 4;
    const int b_row_l = (lane & 7) + ((lane & 16) >> 1);
    const int b_ks_l  = (lane >> 3) & 1;

    // precomputed loader offsets
    uint32_t ag[4], as[4], bg[4], bs[4];
    #pragma unroll
    for (int j = 0; j < 4; j++) {
        int i = tid + j * 256;
        int kseg = i & 7, site = (i >> 3) & 31, t = i >> 8;
        ag[j] = (uint32_t)((t * BROWS + bm0 + site) * 2048 + kseg * 16);
        as[j] = (uint32_t)(t * 4096 + sw_off(site, kseg));
        int n = i >> 3;
        bg[j] = (uint32_t)((bn0 + n) * 4096 + kseg * 16);
        bs[j] = sw_off(n, kseg);
    }

    auto load_chunk = [&](int cc, int buf) {
        const uint32_t acol = (cc & 15) * 128;
        const uint32_t bcol = cc * 128;
        const uint32_t abase = sbase + buf * A2_STAGE;
        const uint32_t bbase = sbase + SM2_B + buf * B2_STAGE;
        #pragma unroll
        for (int j = 0; j < 4; j++)
            CP_ASYNC16(abase + as[j], (const char*)A + ag[j] + acol);
        #pragma unroll
        for (int j = 0; j < 4; j++)
            CP_ASYNC16(bbase + bs[j], (const char*)Bw + bg[j] + bcol);
        CP_COMMIT();
    };

    int acc[TT][4][4];
    #pragma unroll
    for (int t = 0; t < TT; t++)
        #pragma unroll
        for (int n = 0; n < 4; n++)
            #pragma unroll
            for (int e = 0; e < 4; e++) acc[t][n][e] = 0;

    load_chunk(0, 0);
    load_chunk(1, 1);

    int buf = 0, pbuf = 2;
    for (int cc = 0; cc < NC; cc++) {
        if (cc < NC - 1) asm volatile("cp.async.wait_group 1;" ::: "memory");
        else             asm volatile("cp.async.wait_group 0;" ::: "memory");
        __syncthreads();
        if (cc + 2 < NC) load_chunk(cc + 2, pbuf);

        #pragma unroll
        for (int ks = 0; ks < 4; ks++) {
            uint32_t b[4][2];
            #pragma unroll
            for (int p = 0; p < 2; p++) {
                uint32_t addr = sbase + SM2_B + buf * B2_STAGE +
                    sw_off(nn_w + p * 16 + b_row_l, 2 * ks + b_ks_l);
                LDSM_X4(b[2*p][0], b[2*p][1], b[2*p+1][0], b[2*p+1][1], addr);
            }
            uint32_t a[TT][4];
            #pragma unroll
            for (int t = 0; t < TT; t++) {
                uint32_t addr = sbase + buf * A2_STAGE + t * 4096 +
                    sw_off(sm_w + a_row_l, 2 * ks + a_ks_l);
                LDSM_X4(a[t][0], a[t][1], a[t][2], a[t][3], addr);
            }
            #pragma unroll
            for (int t = 0; t < TT; t++)
                #pragma unroll
                for (int n = 0; n < 4; n++)
                    IMMA16832(acc[t][n], a[t], b[n]);
        }

        if (cc == 15) {                 // exact digit fold
            #pragma unroll
            for (int t = 0; t < TT; t++)
                #pragma unroll
                for (int n = 0; n < 4; n++)
                    #pragma unroll
                    for (int e = 0; e < 4; e++) acc[t][n][e] <<= 7;
        }
        buf = (buf == STG - 1) ? 0 : buf + 1;
        pbuf = (pbuf == STG - 1) ? 0 : pbuf + 1;
    }

    // PLIF scan on y = acc * 2^-15, store spikes, flag tight margins
    const float alpha = alphap[0];
    const int row_in_m = lane >> 2;
    const int col_pair = (lane & 3) * 2;
    #pragma unroll
    for (int n = 0; n < 4; n++)
        #pragma unroll
        for (int rh = 0; rh < 2; rh++) {
            const int site = bm0 + sm_w + row_in_m + rh * 8;
            const int col  = bn0 + nn_w + n * 8 + col_pair;
            float v0 = 0.f, v1 = 0.f, m0 = 1e9f, m1 = 1e9f;
            #pragma unroll
            for (int t = 0; t < TT; t++) {
                float y0 = (float)acc[t][n][rh * 2]     * W2SCALE;
                float y1 = (float)acc[t][n][rh * 2 + 1] * W2SCALE;
                v0 += alpha * (y0 - v0);
                v1 += alpha * (y1 - v1);
                m0 = fminf(m0, fabsf(v0 - 1.0f));
                m1 = fminf(m1, fabsf(v1 - 1.0f));
                bool s0 = (v0 >= 1.0f), s1v = (v1 >= 1.0f);
                v0 = s0 ? 0.f : v0;
                v1 = s1v ? 0.f : v1;
                *(float2*)(outp + ((size_t)t * BROWS + site) * DD + col) =
                    make_float2(s0 ? 1.0f : 0.0f, s1v ? 1.0f : 0.0f);
            }
            push_flag(m0 < EPS2, site * 512 + col,     &g_cnt2, g_list2);
            push_flag(m1 < EPS2, site * 512 + col + 1, &g_cnt2, g_list2);
        }
}

// ---------------- repair2: t-parallel exact recompute of out ----------------
__global__ void repair_l2(const int8_t* __restrict__ s1,
                          const float* __restrict__ w2raw,
                          const float* __restrict__ alphap,
                          float* __restrict__ outp)
{
    const int total = min(g_cnt2, LCAP);
    const float alpha = alphap[0];
    const int lane = threadIdx.x & 31;
    const int tg   = lane >> 3;
    const int gl   = lane & 7;
    const int nwarp = (gridDim.x * blockDim.x) >> 5;
    for (int w = (blockIdx.x * blockDim.x + threadIdx.x) >> 5; w < total; w += nwarp) {
        const int e = g_list2[w];
        const int site = e >> 9, col = e & 511;
        const float4* wp = (const float4*)(w2raw + (size_t)col * 2048);
        const char4* sp = (const char4*)(s1 + ((size_t)tg * BROWS + site) * HH);
        float p = 0.f;
        #pragma unroll
        for (int k = 0; k < 64; k += 8) {
            char4 sv = sp[gl + k * 8];
            float4 wv = wp[gl + k * 8];
            if (sv.x) p += wv.x;
            if (sv.y) p += wv.y;
            if (sv.z) p += wv.z;
            if (sv.w) p += wv.w;
        }
        p += __shfl_xor_sync(0xFFFFFFFF, p, 4);
        p += __shfl_xor_sync(0xFFFFFFFF, p, 2);
        p += __shfl_xor_sync(0xFFFFFFFF, p, 1);
        float h0 = __shfl_sync(0xFFFFFFFF, p, 0);
        float h1 = __shfl_sync(0xFFFFFFFF, p, 8);
        float h2 = __shfl_sync(0xFFFFFFFF, p, 16);
        float h3 = __shfl_sync(0xFFFFFFFF, p, 24);
        if (lane == 0) {
            float h[4] = {h0, h1, h2, h3};
            float v = 0.f;
            #pragma unroll
            for (int t = 0; t < TT; t++) {
                v += alpha * (h[t] - v);
                bool s = (v >= 1.0f);
                outp[((size_t)t * BROWS + site) * DD + col] = s ? 1.0f : 0.0f;
                v = s ? 0.f : v;
            }
        }
    }
}

// ---------------- launch ----------------
extern "C" void kernel_launch(void* const* d_in, const int* in_sizes, int n_in,
                              void* d_out, int out_size)
{
    const float* x  = (const float*)d_in[0];
    const float* W1 = (const float*)d_in[1];
    const float* W2 = (const float*)d_in[2];
    const float* a1 = (const float*)d_in[3];
    const float* a2 = (const float*)d_in[4];
    float* out = (float*)d_out;

    __half *xh, *w1h;
    int8_t *xq, *w1q, *w2p, *s1;
    cudaGetSymbolAddress((void**)&xh,  g_xh);
    cudaGetSymbolAddress((void**)&xq,  g_xq);
    cudaGetSymbolAddress((void**)&w1h, g_w1h);
    cudaGetSymbolAddress((void**)&w1q, g_w1q);
    cudaGetSymbolAddress((void**)&w2p, g_w2);
    cudaGetSymbolAddress((void**)&s1,  g_s1);

    cudaFuncSetAttribute(gemm_plif_l1, cudaFuncAttributeMaxDynamicSharedMemorySize, SMEM1);
    cudaFuncSetAttribute(gemm_plif_l2, cudaFuncAttributeMaxDynamicSharedMemorySize, SMEM2);

    prep_all<<<24576, 256>>>((const float4*)x, xh, xq, W1, w1h, w1q, W2, w2p);

    // layer 1: int8 cross (K=1024) + fp16 hi*hi (K=512) -> s1 + flags
    dim3 g1(BROWS / MS1, HH / TN1);   // 256 x 16
    gemm_plif_l1<<<g1, 256, SMEM1>>>(xq, w1q, xh, w1h, a1, s1);
    repair_l1<<<256, 256>>>(x, W1, a1, s1);

    // layer 2: int8 IMMA 2-digit (K=4096) -> out + flags
    dim3 g2(BROWS / MS2, DD / TN2);   // 256 x 4
    gemm_plif_l2<<<g2, 256, SMEM2>>>(s1, w2p, a2, out);
    repair_l2<<<256, 256>>>(s1, W2, a2, out);
}

// round 17
// speedup vs baseline: 1.0031x; 1.0031x over previous
#include <cuda_runtime.h>
#include <cuda_bf16.h>
#include <cuda_fp16.h>
#include <cstdint>
#include <cstddef>

// ---------------- problem dims ----------------
constexpr int TT    = 4;
constexpr int BROWS = 8192;
constexpr int DD    = 512;
constexpr int HH    = 2048;
constexpr int KQ1   = 1024;           // layer1 int8 K: [q(lx) | q(x)]
constexpr int KH1   = 512;            // layer1 fp16 K (hi*hi)
constexpr int KA2   = 2048;           // layer2 A cols (s1 int8, wraps)
constexpr int KB2   = 4096;           // layer2 K: 2 digit planes x 2048 int8

// layer1 scales (fold constraint: 1/(IXL*IWH) == 1/(IXH*IWL), exact)
constexpr float IXH = 127.0f / 8.0f;
constexpr float IXL = 40000.0f;
constexpr float IWH = 127.0f / 0.32f;
constexpr float IWL = 1000000.0f;
constexpr float CFOLD = 8.0f / (127.0f * 1000000.0f);
constexpr float EPS1 = 2.5e-4f;
constexpr float W2SCALE = 1.0f / 32768.0f;
constexpr float EPS2 = 4e-3f;

// ---- layer1 tile: CTA 32 x 128 x 4t, 8 warps of 16x32, STG=3, 2 CTAs/SM ----
constexpr int MS1 = 32, TN1 = 128, STG = 3;
constexpr uint32_t A1_STAGE = 16384;
constexpr uint32_t B1_STAGE = 16384;
constexpr uint32_t SM1_B = STG * A1_STAGE;
constexpr uint32_t SMEM1 = STG * (A1_STAGE + B1_STAGE);   // 98304

// ---- layer2 tile ----
constexpr int MS2 = 32, TN2 = 128, BK2 = 128;
constexpr uint32_t A2_STAGE = 16384;
constexpr uint32_t B2_STAGE = 16384;
constexpr uint32_t SM2_B = STG * A2_STAGE;
constexpr uint32_t SMEM2 = STG * (A2_STAGE + B2_STAGE);   // 98304

// ---------------- scratch ----------------
__device__ __half  g_xh[(size_t)TT * BROWS * KH1];
__device__ int8_t  g_xq[(size_t)TT * BROWS * KQ1];
__device__ __half  g_w1h[(size_t)HH * KH1];
__device__ int8_t  g_w1q[(size_t)HH * KQ1];
__device__ int8_t  g_w2[(size_t)DD * KB2];
__device__ int8_t  g_s1[(size_t)TT * BROWS * HH];
constexpr int LCAP = 1 << 22;
__device__ int g_cnt1, g_cnt2;
__device__ int g_list1[LCAP];
__device__ int g_list2[LCAP];

// ---------------- PTX helpers ----------------
__device__ __forceinline__ uint32_t smem_u32(const void* p) {
    uint32_t a;
    asm("{ .reg .u64 t; cvta.to.shared.u64 t, %1; cvt.u32.u64 %0, t; }" : "=r"(a) : "l"(p));
    return a;
}
#define CP_ASYNC16(dst, src) \
    asm volatile("cp.async.cg.shared.global [%0], [%1], 16;" :: "r"(dst), "l"(src) : "memory")
#define CP_COMMIT() asm volatile("cp.async.commit_group;" ::: "memory")

#define LDSM_X4(r0, r1, r2, r3, addr)                                        \
    asm volatile("ldmatrix.sync.aligned.m8n8.x4.shared.b16 {%0,%1,%2,%3}, [%4];" \
        : "=r"(r0), "=r"(r1), "=r"(r2), "=r"(r3) : "r"(addr))

#define MMAF16(d, a, b)                                                      \
    asm volatile("mma.sync.aligned.m16n8k16.row.col.f32.f16.f16.f32 "        \
        "{%0,%1,%2,%3}, {%4,%5,%6,%7}, {%8,%9}, {%0,%1,%2,%3};"              \
        : "+f"((d)[0]), "+f"((d)[1]), "+f"((d)[2]), "+f"((d)[3])             \
        : "r"((a)[0]), "r"((a)[1]), "r"((a)[2]), "r"((a)[3]),                \
          "r"((b)[0]), "r"((b)[1]))

#define IMMA16832(d, a, b)                                                   \
    asm volatile("mma.sync.aligned.m16n8k32.row.col.s32.s8.s8.s32 "          \
        "{%0,%1,%2,%3}, {%4,%5,%6,%7}, {%8,%9}, {%0,%1,%2,%3};"              \
        : "+r"((d)[0]), "+r"((d)[1]), "+r"((d)[2]), "+r"((d)[3])             \
        : "r"((a)[0]), "r"((a)[1]), "r"((a)[2]), "r"((a)[3]),                \
          "r"((b)[0]), "r"((b)[1]))

__device__ __forceinline__ uint32_t sw_off(uint32_t row, uint32_t kseg) {
    return row * 128 + ((kseg ^ (row & 7)) << 4);
}
__device__ __forceinline__ int8_t q8(float v, float inv) {
    int q = __float2int_rn(v * inv);
    q = max(-127, min(127, q));
    return (int8_t)q;
}
// warp-aggregated flag push (flags are rare; early-out on no-flag)
__device__ __forceinline__ void push_flag(bool flag, int val, int* cnt, int* list) {
    unsigned bal = __ballot_sync(0xFFFFFFFF, flag);
    if (!bal) return;
    int leader = __ffs(bal) - 1;
    int lane = threadIdx.x & 31;
    int base = 0;
    if (lane == leader) base = atomicAdd(cnt, __popc(bal));
    base = __shfl_sync(0xFFFFFFFF, base, leader);
    if (flag) {
        int idx = base + __popc(bal & ((1u << lane) - 1));
        if (idx < LCAP) list[idx] = val;
    }
}

// ---------------- prep kernels (R15 measured-best arrangement) ----------------
__global__ void prep_x(const float4* __restrict__ x,
                       __half* __restrict__ xh,
                       int8_t* __restrict__ xq)
{
    if (blockIdx.x == 0 && threadIdx.x == 0) { g_cnt1 = 0; g_cnt2 = 0; }
    size_t i = (size_t)blockIdx.x * blockDim.x + threadIdx.x;
    float4 v = x[i];
    int r = (int)(i >> 7);
    int d = ((int)i & 127) * 4;
    __half h0 = __float2half_rn(v.x), h1 = __float2half_rn(v.y);
    __half h2 = __float2half_rn(v.z), h3 = __float2half_rn(v.w);
    __half2* hp = (__half2*)(xh + (size_t)r * KH1 + d);
    hp[0] = __halves2half2(h0, h1);
    hp[1] = __halves2half2(h2, h3);
    float l0 = v.x - __half2float(h0), l1 = v.y - __half2float(h1);
    float l2 = v.z - __half2float(h2), l3 = v.w - __half2float(h3);
    char4 ql = make_char4(q8(l0, IXL), q8(l1, IXL), q8(l2, IXL), q8(l3, IXL));
    char4 qx = make_char4(q8(v.x, IXH), q8(v.y, IXH), q8(v.z, IXH), q8(v.w, IXH));
    *(char4*)(xq + (size_t)r * KQ1 + d)       = ql;
    *(char4*)(xq + (size_t)r * KQ1 + 512 + d) = qx;
}
// merged W prep: blocks [0, 4096) -> w1 split/quant; [4096, 8192) -> w2 digits
__global__ void prep_w(const float* __restrict__ w1,
                       __half* __restrict__ wh,
                       int8_t* __restrict__ wq,
                       const float* __restrict__ w2,
                       int8_t* __restrict__ o2)
{
    if (blockIdx.x < 4096) {
        size_t i = (size_t)blockIdx.x * blockDim.x + threadIdx.x;   // 2048*512
        int r = (int)(i >> 9);
        int d = (int)(i & 511);
        float v = w1[i];
        __half hb = __float2half_rn(v);
        float hi = __half2float(hb);
        wh[(size_t)r * KH1 + d] = hb;
        wq[(size_t)r * KQ1 + d]       = q8(hi, IWH);
        wq[(size_t)r * KQ1 + 512 + d] = q8(v - hi, IWL);
    } else {
        size_t i = (size_t)(blockIdx.x - 4096) * blockDim.x + threadIdx.x; // 512*2048
        int r = (int)(i >> 11);
        int c = (int)(i & 2047);
        int v = (int)lrintf(w2[i] * 32768.0f);
        v = max(-8192, min(8192, v));
        int d0 = ((v & 127) ^ 64) - 64;
        int d1 = (v - d0) >> 7;
        size_t base = (size_t)r * KB2;
        o2[base + c]        = (int8_t)d1;
        o2[base + 2048 + c] = (int8_t)d0;
    }
}

// ---------------- layer1: unified int8+fp16 pipeline, 2 CTAs/SM ----------------
__global__ __launch_bounds__(256, 2)
void gemm_plif_l1(const void* __restrict__ Aq, const void* __restrict__ Bq,
                  const void* __restrict__ Ah, const void* __restrict__ Bh,
                  const float* __restrict__ alphap,
                  int8_t* __restrict__ outp)
{
    extern __shared__ __align__(128) unsigned char smem_raw[];
    const uint32_t sbase = smem_u32(smem_raw);

    const int tid  = threadIdx.x;
    const int lane = tid & 31;
    const int wid  = tid >> 5;
    const int wm   = wid & 1;
    const int wn   = wid >> 1;
    const int sm_w = wm * 16;
    const int nn_w = wn * 32;

    const int bm0 = blockIdx.x * MS1;
    const int bn0 = blockIdx.y * TN1;

    const int a_row_l = lane & 15;
    const int a_ks_l  = lane >> 4;
    const int b_row_l = (lane & 7) + ((lane & 16) >> 1);
    const int b_ks_l  = (lane >> 3) & 1;

    // ---- precomputed loader offsets (chunk-invariant) ----
    uint32_t ag[4], as[4], bg[4], bs[4];
    #pragma unroll
    for (int j = 0; j < 4; j++) {
        int i = tid + j * 256;
        int kseg = i & 7, site = (i >> 3) & 31, t = i >> 8;
        ag[j] = (uint32_t)((t * BROWS + bm0 + site) * 1024 + kseg * 16);
        as[j] = (uint32_t)(t * 4096 + sw_off(site, kseg));
        int n = i >> 3;
        bg[j] = (uint32_t)((bn0 + n) * 1024 + kseg * 16);
        bs[j] = sw_off(n, kseg);
    }

    auto load_chunk = [&](int cc, int buf) {
        const char* Ab = (const char*)((cc < 8) ? Aq : Ah);
        const char* Bb = (const char*)((cc < 8) ? Bq : Bh);
        const uint32_t bcol = (cc & 7) * 128;
        const uint32_t abase = sbase + buf * A1_STAGE;
        const uint32_t bbase = sbase + SM1_B + buf * B1_STAGE;
        #pragma unroll
        for (int j = 0; j < 4; j++)
            CP_ASYNC16(abase + as[j], Ab + ag[j] + bcol);
        #pragma unroll
        for (int j = 0; j < 4; j++)
            CP_ASYNC16(bbase + bs[j], Bb + bg[j] + bcol);
        CP_COMMIT();
    };

    float accf[TT][4][4];
    load_chunk(0, 0);
    load_chunk(1, 1);

    {   // ---- int8 phase: chunks 0-7 (ring continues into fp16 chunks) ----
        int acci[TT][4][4];
        #pragma unroll
        for (int t = 0; t < TT; t++)
            #pragma unroll
            for (int n = 0; n < 4; n++)
                #pragma unroll
                for (int e = 0; e < 4; e++) acci[t][n][e] = 0;

        int buf = 0, pbuf = 2;
        for (int cc = 0; cc < 8; cc++) {
            asm volatile("cp.async.wait_group 1;" ::: "memory");
            __syncthreads();
            load_chunk(cc + 2, pbuf);

            #pragma unroll
            for (int ks = 0; ks < 4; ks++) {
                uint32_t b[4][2];
                #pragma unroll
                for (int p = 0; p < 2; p++) {
                    uint32_t addr = sbase + SM1_B + buf * B1_STAGE +
                        sw_off(nn_w + p * 16 + b_row_l, 2 * ks + b_ks_l);
                    LDSM_X4(b[2*p][0], b[2*p][1], b[2*p+1][0], b[2*p+1][1], addr);
                }
                uint32_t a[TT][4];
                #pragma unroll
                for (int t = 0; t < TT; t++) {
                    uint32_t addr = sbase + buf * A1_STAGE + t * 4096 +
                        sw_off(sm_w + a_row_l, 2 * ks + a_ks_l);
                    LDSM_X4(a[t][0], a[t][1], a[t][2], a[t][3], addr);
                }
                #pragma unroll
                for (int t = 0; t < TT; t++)
                    #pragma unroll
                    for (int n = 0; n < 4; n++)
                        IMMA16832(acci[t][n], a[t], b[n]);
            }
            buf = (buf == STG - 1) ? 0 : buf + 1;
            pbuf = (pbuf == STG - 1) ? 0 : pbuf + 1;
        }
        // fold: acci dies here, accf born here (disjoint live ranges)
        #pragma unroll
        for (int t = 0; t < TT; t++)
            #pragma unroll
            for (int n = 0; n < 4; n++)
                #pragma unroll
                for (int e = 0; e < 4; e++)
                    accf[t][n][e] = CFOLD * (float)acci[t][n][e];
    }

    // ---- fp16 phase: chunks 8-15, same ring, no drain ----
    {
        int buf = 8 % STG, pbuf = 10 % STG;
        for (int cc = 8; cc < 16; cc++) {
            if (cc < 15) asm volatile("cp.async.wait_group 1;" ::: "memory");
            else         asm volatile("cp.async.wait_group 0;" ::: "memory");
            __syncthreads();
            if (cc + 2 < 16) load_chunk(cc + 2, pbuf);

            #pragma unroll
            for (int ks = 0; ks < 4; ks++) {
                uint32_t b[4][2];
                #pragma unroll
                for (int p = 0; p < 2; p++) {
                    uint32_t addr = sbase + SM1_B + buf * B1_STAGE +
                        sw_off(nn_w + p * 16 + b_row_l, 2 * ks + b_ks_l);
                    LDSM_X4(b[2*p][0], b[2*p][1], b[2*p+1][0], b[2*p+1][1], addr);
                }
                uint32_t a[TT][4];
                #pragma unroll
                for (int t = 0; t < TT; t++) {
                    uint32_t addr = sbase + buf * A1_STAGE + t * 4096 +
                        sw_off(sm_w + a_row_l, 2 * ks + a_ks_l);
                    LDSM_X4(a[t][0], a[t][1], a[t][2], a[t][3], addr);
                }
                #pragma unroll
                for (int t = 0; t < TT; t++)
                    #pragma unroll
                    for (int n = 0; n < 4; n++)
                        MMAF16(accf[t][n], a[t], b[n]);
            }
            buf = (buf == STG - 1) ? 0 : buf + 1;
            pbuf = (pbuf == STG - 1) ? 0 : pbuf + 1;
        }
    }

    // ---- epilogue: scan, store spikes, flag tight margins ----
    const float alpha = alphap[0];
    const int row_in_m = lane >> 2;
    const int col_pair = (lane & 3) * 2;

    #pragma unroll
    for (int n = 0; n < 4; n++)
        #pragma unroll
        for (int rh = 0; rh < 2; rh++) {
            const int site = bm0 + sm_w + row_in_m + rh * 8;
            const int col  = bn0 + nn_w + n * 8 + col_pair;
            float v0 = 0.f, v1 = 0.f, m0 = 1e9f, m1 = 1e9f;
            #pragma unroll
            for (int t = 0; t < TT; t++) {
                v0 += alpha * (accf[t][n][rh * 2]     - v0);
                v1 += alpha * (accf[t][n][rh * 2 + 1] - v1);
                m0 = fminf(m0, fabsf(v0 - 1.0f));
                m1 = fminf(m1, fabsf(v1 - 1.0f));
                bool s0 = (v0 >= 1.0f), s1 = (v1 >= 1.0f);
                v0 = s0 ? 0.f : v0;
                v1 = s1 ? 0.f : v1;
                char2 pk;
                pk.x = s0 ? 1 : 0;
                pk.y = s1 ? 1 : 0;
                *(char2*)(outp + ((size_t)t * BROWS + site) * HH + col) = pk;
            }
            push_flag(m0 < EPS1, site * 2048 + col,     &g_cnt1, g_list1);
            push_flag(m1 < EPS1, site * 2048 + col + 1, &g_cnt1, g_list1);
        }
}

// ---------------- repair1: t-parallel exact fp32 recompute ----------------
// 4 groups of 8 lanes, one timestep each (4x memory-level parallelism).
__global__ void repair_l1(const float* __restrict__ xraw,
                          const float* __restrict__ w1raw,
                          const float* __restrict__ alphap,
                          int8_t* __restrict__ s1)
{
    const int total = min(g_cnt1, LCAP);
    const float alpha = alphap[0];
    const int lane = threadIdx.x & 31;
    const int tg   = lane >> 3;          // timestep group 0..3
    const int gl   = lane & 7;           // lane within group
    const int nwarp = (gridDim.x * blockDim.x) >> 5;
    for (int w = (blockIdx.x * blockDim.x + threadIdx.x) >> 5; w < total; w += nwarp) {
        const int e = g_list1[w];
        const int site = e >> 11, neuron = e & 2047;
        const float4* wp = (const float4*)(w1raw + (size_t)neuron * 512);
        const float4* xp = (const float4*)(xraw + ((size_t)tg * BROWS + site) * 512);
        float p = 0.f;
        #pragma unroll
        for (int k = 0; k < 16; k++) {
            float4 xv = xp[gl + k * 8], wv = wp[gl + k * 8];
            p += xv.x * wv.x + xv.y * wv.y + xv.z * wv.z + xv.w * wv.w;
        }
        p += __shfl_xor_sync(0xFFFFFFFF, p, 4);
        p += __shfl_xor_sync(0xFFFFFFFF, p, 2);
        p += __shfl_xor_sync(0xFFFFFFFF, p, 1);
        float h0 = __shfl_sync(0xFFFFFFFF, p, 0);
        float h1 = __shfl_sync(0xFFFFFFFF, p, 8);
        float h2 = __shfl_sync(0xFFFFFFFF, p, 16);
        float h3 = __shfl_sync(0xFFFFFFFF, p, 24);
        if (lane == 0) {
            float h[4] = {h0, h1, h2, h3};
            float v = 0.f;
            #pragma unroll
            for (int t = 0; t < TT; t++) {
                v += alpha * (h[t] - v);
                bool s = (v >= 1.0f);
                s1[((size_t)t * BROWS + site) * HH + neuron] = s ? 1 : 0;
                v = s ? 0.f : v;
            }
        }
    }
}

// ---------------- layer2: int8 IMMA 2-digit + PLIF + flag, 2 CTAs/SM ----------------
__global__ __launch_bounds__(256, 2)
void gemm_plif_l2(const int8_t* __restrict__ A,
                  const int8_t* __restrict__ Bw,
                  const float* __restrict__ alphap,
                  float* __restrict__ outp)
{
    extern __shared__ __align__(128) unsigned char smem_raw[];
    const uint32_t sbase = smem_u32(smem_raw);

    const int tid  = threadIdx.x;
    const int lane = tid & 31;
    const int wid  = tid >> 5;
    const int wm   = wid & 1;
    const int wn   = wid >> 1;
    const int sm_w = wm * 16;
    const int nn_w = wn * 32;

    const int bm0 = blockIdx.x * MS2;
    const int bn0 = blockIdx.y * TN2;
    const int NC  = KB2 / BK2;          // 32; digit fold at cc==15

    const int a_row_l = lane & 15;
    const int a_ks_l  = lane >> 4;
    const int b_row_l = (lane & 7) + ((lane & 16) >> 1);
    const int b_ks_l  = (lane >> 3) & 1;

    // precomputed loader offsets
    uint32_t ag[4], as[4], bg[4], bs[4];
    #pragma unroll
    for (int j = 0; j < 4; j++) {
        int i = tid + j * 256;
        int kseg = i & 7, site = (i >> 3) & 31, t = i >> 8;
        ag[j] = (uint32_t)((t * BROWS + bm0 + site) * 2048 + kseg * 16);
        as[j] = (uint32_t)(t * 4096 + sw_off(site, kseg));
        int n = i >> 3;
        bg[j] = (uint32_t)((bn0 + n) * 4096 + kseg * 16);
        bs[j] = sw_off(n, kseg);
    }

    auto load_chunk = [&](int cc, int buf) {
        const uint32_t acol = (cc & 15) * 128;
        const uint32_t bcol = cc * 128;
        const uint32_t abase = sbase + buf * A2_STAGE;
        const uint32_t bbase = sbase + SM2_B + buf * B2_STAGE;
        #pragma unroll
        for (int j = 0; j < 4; j++)
            CP_ASYNC16(abase + as[j], (const char*)A + ag[j] + acol);
        #pragma unroll
        for (int j = 0; j < 4; j++)
            CP_ASYNC16(bbase + bs[j], (const char*)Bw + bg[j] + bcol);
        CP_COMMIT();
    };

    int acc[TT][4][4];
    #pragma unroll
    for (int t = 0; t < TT; t++)
        #pragma unroll
        for (int n = 0; n < 4; n++)
            #pragma unroll
            for (int e = 0; e < 4; e++) acc[t][n][e] = 0;

    load_chunk(0, 0);
    load_chunk(1, 1);

    int buf = 0, pbuf = 2;
    for (int cc = 0; cc < NC; cc++) {
        if (cc < NC - 1) asm volatile("cp.async.wait_group 1;" ::: "memory");
        else             asm volatile("cp.async.wait_group 0;" ::: "memory");
        __syncthreads();
        if (cc + 2 < NC) load_chunk(cc + 2, pbuf);

        #pragma unroll
        for (int ks = 0; ks < 4; ks++) {
            uint32_t b[4][2];
            #pragma unroll
            for (int p = 0; p < 2; p++) {
                uint32_t addr = sbase + SM2_B + buf * B2_STAGE +
                    sw_off(nn_w + p * 16 + b_row_l, 2 * ks + b_ks_l);
                LDSM_X4(b[2*p][0], b[2*p][1], b[2*p+1][0], b[2*p+1][1], addr);
            }
            uint32_t a[TT][4];
            #pragma unroll
            for (int t = 0; t < TT; t++) {
                uint32_t addr = sbase + buf * A2_STAGE + t * 4096 +
                    sw_off(sm_w + a_row_l, 2 * ks + a_ks_l);
                LDSM_X4(a[t][0], a[t][1], a[t][2], a[t][3], addr);
            }
            #pragma unroll
            for (int t = 0; t < TT; t++)
                #pragma unroll
                for (int n = 0; n < 4; n++)
                    IMMA16832(acc[t][n], a[t], b[n]);
        }

        if (cc == 15) {                 // exact digit fold
            #pragma unroll
            for (int t = 0; t < TT; t++)
                #pragma unroll
                for (int n = 0; n < 4; n++)
                    #pragma unroll
                    for (int e = 0; e < 4; e++) acc[t][n][e] <<= 7;
        }
        buf = (buf == STG - 1) ? 0 : buf + 1;
        pbuf = (pbuf == STG - 1) ? 0 : pbuf + 1;
    }

    // PLIF scan on y = acc * 2^-15, store spikes, flag tight margins
    const float alpha = alphap[0];
    const int row_in_m = lane >> 2;
    const int col_pair = (lane & 3) * 2;
    #pragma unroll
    for (int n = 0; n < 4; n++)
        #pragma unroll
        for (int rh = 0; rh < 2; rh++) {
            const int site = bm0 + sm_w + row_in_m + rh * 8;
            const int col  = bn0 + nn_w + n * 8 + col_pair;
            float v0 = 0.f, v1 = 0.f, m0 = 1e9f, m1 = 1e9f;
            #pragma unroll
            for (int t = 0; t < TT; t++) {
                float y0 = (float)acc[t][n][rh * 2]     * W2SCALE;
                float y1 = (float)acc[t][n][rh * 2 + 1] * W2SCALE;
                v0 += alpha * (y0 - v0);
                v1 += alpha * (y1 - v1);
                m0 = fminf(m0, fabsf(v0 - 1.0f));
                m1 = fminf(m1, fabsf(v1 - 1.0f));
                bool s0 = (v0 >= 1.0f), s1v = (v1 >= 1.0f);
                v0 = s0 ? 0.f : v0;
                v1 = s1v ? 0.f : v1;
                *(float2*)(outp + ((size_t)t * BROWS + site) * DD + col) =
                    make_float2(s0 ? 1.0f : 0.0f, s1v ? 1.0f : 0.0f);
            }
            push_flag(m0 < EPS2, site * 512 + col,     &g_cnt2, g_list2);
            push_flag(m1 < EPS2, site * 512 + col + 1, &g_cnt2, g_list2);
        }
}

// ---------------- repair2: t-parallel exact recompute of out ----------------
__global__ void repair_l2(const int8_t* __restrict__ s1,
                          const float* __restrict__ w2raw,
                          const float* __restrict__ alphap,
                          float* __restrict__ outp)
{
    const int total = min(g_cnt2, LCAP);
    const float alpha = alphap[0];
    const int lane = threadIdx.x & 31;
    const int tg   = lane >> 3;
    const int gl   = lane & 7;
    const int nwarp = (gridDim.x * blockDim.x) >> 5;
    for (int w = (blockIdx.x * blockDim.x + threadIdx.x) >> 5; w < total; w += nwarp) {
        const int e = g_list2[w];
        const int site = e >> 9, col = e & 511;
        const float4* wp = (const float4*)(w2raw + (size_t)col * 2048);
        const char4* sp = (const char4*)(s1 + ((size_t)tg * BROWS + site) * HH);
        float p = 0.f;
        #pragma unroll
        for (int k = 0; k < 64; k += 8) {
            char4 sv = sp[gl + k * 8];
            float4 wv = wp[gl + k * 8];
            if (sv.x) p += wv.x;
            if (sv.y) p += wv.y;
            if (sv.z) p += wv.z;
            if (sv.w) p += wv.w;
        }
        p += __shfl_xor_sync(0xFFFFFFFF, p, 4);
        p += __shfl_xor_sync(0xFFFFFFFF, p, 2);
        p += __shfl_xor_sync(0xFFFFFFFF, p, 1);
        float h0 = __shfl_sync(0xFFFFFFFF, p, 0);
        float h1 = __shfl_sync(0xFFFFFFFF, p, 8);
        float h2 = __shfl_sync(0xFFFFFFFF, p, 16);
        float h3 = __shfl_sync(0xFFFFFFFF, p, 24);
        if (lane == 0) {
            float h[4] = {h0, h1, h2, h3};
            float v = 0.f;
            #pragma unroll
            for (int t = 0; t < TT; t++) {
                v += alpha * (h[t] - v);
                bool s = (v >= 1.0f);
                outp[((size_t)t * BROWS + site) * DD + col] = s ? 1.0f : 0.0f;
                v = s ? 0.f : v;
            }
        }
    }
}

// ---------------- launch ----------------
extern "C" void kernel_launch(void* const* d_in, const int* in_sizes, int n_in,
                              void* d_out, int out_size)
{
    const float* x  = (const float*)d_in[0];
    const float* W1 = (const float*)d_in[1];
    const float* W2 = (const float*)d_in[2];
    const float* a1 = (const float*)d_in[3];
    const float* a2 = (const float*)d_in[4];
    float* out = (float*)d_out;

    __half *xh, *w1h;
    int8_t *xq, *w1q, *w2p, *s1;
    cudaGetSymbolAddress((void**)&xh,  g_xh);
    cudaGetSymbolAddress((void**)&xq,  g_xq);
    cudaGetSymbolAddress((void**)&w1h, g_w1h);
    cudaGetSymbolAddress((void**)&w1q, g_w1q);
    cudaGetSymbolAddress((void**)&w2p, g_w2);
    cudaGetSymbolAddress((void**)&s1,  g_s1);

    cudaFuncSetAttribute(gemm_plif_l1, cudaFuncAttributeMaxDynamicSharedMemorySize, SMEM1);
    cudaFuncSetAttribute(gemm_plif_l2, cudaFuncAttributeMaxDynamicSharedMemorySize, SMEM2);

    prep_x<<<(TT * BROWS * DD / 4) / 256, 256>>>((const float4*)x, xh, xq);
    prep_w<<<8192, 256>>>(W1, w1h, w1q, W2, w2p);

    // layer 1: int8 cross (K=1024) + fp16 hi*hi (K=512) -> s1 + flags
    dim3 g1(BROWS / MS1, HH / TN1);   // 256 x 16
    gemm_plif_l1<<<g1, 256, SMEM1>>>(xq, w1q, xh, w1h, a1, s1);
    repair_l1<<<256, 256>>>(x, W1, a1, s1);

    // layer 2: int8 IMMA 2-digit (K=4096) -> out + flags
    dim3 g2(BROWS / MS2, DD / TN2);   // 256 x 4
    gemm_plif_l2<<<g2, 256, SMEM2>>>(s1, w2p, a2, out);
    repair_l2<<<256, 256>>>(s1, W2, a2, out);
}